// round 16
// baseline (speedup 1.0000x reference)
#include <cuda_runtime.h>
#include <cuda_fp16.h>
#include <stdint.h>
#include <math.h>

#define NWIN     2048
#define NTOK     66
#define CDIM     256
#define NHEAD    8
#define NTHREADS 512

// fp16 weight copies, prepared at the start of every launch (graph-safe, deterministic)
__device__ __align__(16) __half g_Wq[768 * 256];
__device__ __align__(16) __half g_Wp[256 * 256];

__global__ void prep_kernel(const float* __restrict__ qkv_w,
                            const float* __restrict__ proj_w) {
    int i = blockIdx.x * blockDim.x + threadIdx.x;
    if (i < 768 * 256) g_Wq[i] = __float2half_rn(qkv_w[i]);
    if (i < 256 * 256) g_Wp[i] = __float2half_rn(proj_w[i]);
}

// ---- shared memory layout (byte offsets) ----
// Xs [80][264] h (dead after GEMM1(7): reused as proj chunk2 B)
// Os [80][264] h ; Wh 2 x [96][264] h ; QKV 2 x {Qs[80][40], Ks[72][40], Vt[32][88]}
// Tb fp16[1800] ; IdxT u8[4096] ; Bq fp16[768] ; Bp f32[256]
#define XS_B   0
#define OS_B   42240
#define WH_B   84480
#define WH_STRIDE 25344          // halves (96*264)
#define QKV_B  185856
#define QKV_STR_B 17792          // bytes per buffer
#define TB_B   221440
#define IX_B   225040
#define BQ_B   229136
#define BP_B   230672
#define SMEM_BYTES 231696

__device__ __forceinline__ uint32_t sptr(const void* p) {
    return (uint32_t)__cvta_generic_to_shared(p);
}

#define LDSM4(r0, r1, r2, r3, p)                                              \
    asm volatile("ldmatrix.sync.aligned.m8n8.x4.shared.b16 {%0,%1,%2,%3}, [%4];" \
                 : "=r"(r0), "=r"(r1), "=r"(r2), "=r"(r3) : "r"(sptr(p)))

#define LDSM2(r0, r1, p)                                                      \
    asm volatile("ldmatrix.sync.aligned.m8n8.x2.shared.b16 {%0,%1}, [%2];"    \
                 : "=r"(r0), "=r"(r1) : "r"(sptr(p)))

#define MMA16816(d, a0, a1, a2, a3, b0, b1)                                   \
    asm volatile("mma.sync.aligned.m16n8k16.row.col.f32.f16.f16.f32 "         \
                 "{%0,%1,%2,%3}, {%4,%5,%6,%7}, {%8,%9}, {%0,%1,%2,%3};"      \
                 : "+f"((d)[0]), "+f"((d)[1]), "+f"((d)[2]), "+f"((d)[3])     \
                 : "r"(a0), "r"(a1), "r"(a2), "r"(a3), "r"(b0), "r"(b1))

__device__ __forceinline__ uint32_t pk2(float x, float y) {
    __half2 h = __floats2half2_rn(x, y);
    return *(uint32_t*)&h;
}

// stage one head's qkv weights [96][256] into dst (pitch 264)
__device__ __forceinline__ void stage_head(int head, __half* dst,
                                           int t0, int nthr) {
    for (int i = t0; i < 3072; i += nthr) {
        int o = i >> 5, kk = (i & 31) * 8;
        int s = o >> 5, jj = o & 31;
        *(uint4*)(dst + o * 264 + kk) =
            *(const uint4*)(g_Wq + ((s * 256 + head * 32 + jj) * 256 + kk));
    }
}

// stage proj rows [row0, row0+nrows) into dst (pitch 264)
__device__ __forceinline__ void stage_wp(int row0, int nrows, __half* dst,
                                         int t0, int nthr) {
    for (int i = t0; i < nrows * 32; i += nthr) {
        int o = i >> 5, kk = (i & 31) * 8;
        *(uint4*)(dst + o * 264 + kk) = *(const uint4*)(g_Wp + (row0 + o) * 256 + kk);
    }
}

// GEMM1 column job: n16 column `col` of head h: QKV[80][96-col-slice]
__device__ __forceinline__ void gemm1_col(
    int h, int col, int lane, const __half* __restrict__ Xs,
    const __half* __restrict__ Wc, const __half* __restrict__ Bq,
    __half* __restrict__ Qb, __half* __restrict__ Kb, __half* __restrict__ Vb)
{
    const float scale = 0.17677669529663687f;
    float acc[5][2][4];
#pragma unroll
    for (int i = 0; i < 5; i++)
#pragma unroll
        for (int j = 0; j < 2; j++)
            acc[i][j][0] = acc[i][j][1] = acc[i][j][2] = acc[i][j][3] = 0.f;

    const __half* Brow = Wc + (col * 16 + (lane & 15)) * 264 + ((lane >> 4) * 8);
    const __half* Arow = Xs + (lane & 15) * 264 + ((lane >> 4) * 8);
#pragma unroll
    for (int ks = 0; ks < 16; ks++) {
        uint32_t b0, b1, b2, b3;
        LDSM4(b0, b1, b2, b3, Brow + ks * 16);
#pragma unroll
        for (int mt = 0; mt < 5; mt++) {
            uint32_t a0, a1, a2, a3;
            LDSM4(a0, a1, a2, a3, Arow + mt * 16 * 264 + ks * 16);
            MMA16816(acc[mt][0], a0, a1, a2, a3, b0, b2);
            MMA16816(acc[mt][1], a0, a1, a2, a3, b1, b3);
        }
    }
#pragma unroll
    for (int st = 0; st < 2; st++) {
        int cb = col * 16 + st * 8 + (lane & 3) * 2;
        int s = cb >> 5, dd = cb & 31;
        float b0v = __half2float(Bq[s * 256 + h * 32 + dd]);
        float b1v = __half2float(Bq[s * 256 + h * 32 + dd + 1]);
#pragma unroll
        for (int mt = 0; mt < 5; mt++) {
            int r0 = mt * 16 + (lane >> 2);
#pragma unroll
            for (int part = 0; part < 2; part++) {
                int r = r0 + part * 8;
                float v0 = acc[mt][st][part * 2 + 0] + b0v;
                float v1 = acc[mt][st][part * 2 + 1] + b1v;
                if (s == 0) {
                    *(__half2*)(Qb + r * 40 + dd) =
                        __floats2half2_rn(v0 * scale, v1 * scale);
                } else if (s == 1) {
                    if (r < 72)
                        *(__half2*)(Kb + r * 40 + dd) = __floats2half2_rn(v0, v1);
                } else {
                    Vb[dd * 88 + r]       = __float2half_rn(v0);
                    Vb[(dd + 1) * 88 + r] = __float2half_rn(v1);
                }
            }
        }
    }
}

// attention for m-tile mt of head h, entirely in registers
__device__ __forceinline__ void attn_tile(
    int h, int mt, int lane,
    const __half* __restrict__ Qb, const __half* __restrict__ Kb,
    const __half* __restrict__ Vb, __half* __restrict__ Os,
    const __half* __restrict__ Tb, const unsigned char* __restrict__ IdxT)
{
    const int r0 = mt * 16 + (lane >> 2);
    const int r1 = r0 + 8;
    const int cbase = (lane & 3) * 2;

    const __half* Aq = Qb + (mt * 16 + (lane & 15)) * 40 + ((lane >> 4) * 8);
    uint32_t qa[2][4];
    LDSM4(qa[0][0], qa[0][1], qa[0][2], qa[0][3], Aq);
    LDSM4(qa[1][0], qa[1][1], qa[1][2], qa[1][3], Aq + 16);

    float S[9][4];
#pragma unroll
    for (int nt = 0; nt < 9; nt++) {
        S[nt][0] = S[nt][1] = S[nt][2] = S[nt][3] = 0.f;
        const __half* Bk = Kb + (nt * 8 + (lane & 7)) * 40 + (((lane >> 3) & 1) * 8);
        uint32_t b0, b1;
        LDSM2(b0, b1, Bk);
        MMA16816(S[nt], qa[0][0], qa[0][1], qa[0][2], qa[0][3], b0, b1);
        LDSM2(b0, b1, Bk + 16);
        MMA16816(S[nt], qa[1][0], qa[1][1], qa[1][2], qa[1][3], b0, b1);
    }

#pragma unroll
    for (int nt = 0; nt < 9; nt++) {
#pragma unroll
        for (int e = 0; e < 2; e++) {
            int c = nt * 8 + cbase + e;
            if (c >= 66) {
                S[nt][e] = -1e30f; S[nt][2 + e] = -1e30f;
            } else if (c >= 2) {
                int q = c - 2;
                if (r0 >= 2 && r0 < 66)
                    S[nt][e]     += __half2float(Tb[(int)IdxT[(r0 - 2) * 64 + q] * 8 + h]);
                if (r1 < 66)
                    S[nt][2 + e] += __half2float(Tb[(int)IdxT[(r1 - 2) * 64 + q] * 8 + h]);
            }
        }
    }

    float m0 = -1e30f, m1 = -1e30f;
#pragma unroll
    for (int nt = 0; nt < 9; nt++) {
        m0 = fmaxf(m0, fmaxf(S[nt][0], S[nt][1]));
        m1 = fmaxf(m1, fmaxf(S[nt][2], S[nt][3]));
    }
    m0 = fmaxf(m0, __shfl_xor_sync(0xffffffffu, m0, 1));
    m0 = fmaxf(m0, __shfl_xor_sync(0xffffffffu, m0, 2));
    m1 = fmaxf(m1, __shfl_xor_sync(0xffffffffu, m1, 1));
    m1 = fmaxf(m1, __shfl_xor_sync(0xffffffffu, m1, 2));
    float s0 = 0.f, s1 = 0.f;
#pragma unroll
    for (int nt = 0; nt < 9; nt++) {
        S[nt][0] = __expf(S[nt][0] - m0); s0 += S[nt][0];
        S[nt][1] = __expf(S[nt][1] - m0); s0 += S[nt][1];
        S[nt][2] = __expf(S[nt][2] - m1); s1 += S[nt][2];
        S[nt][3] = __expf(S[nt][3] - m1); s1 += S[nt][3];
    }
    s0 += __shfl_xor_sync(0xffffffffu, s0, 1);
    s0 += __shfl_xor_sync(0xffffffffu, s0, 2);
    s1 += __shfl_xor_sync(0xffffffffu, s1, 1);
    s1 += __shfl_xor_sync(0xffffffffu, s1, 2);
    float inv0 = __frcp_rn(s0), inv1 = __frcp_rn(s1);

    uint32_t pa[5][4];
#pragma unroll
    for (int kt = 0; kt < 5; kt++) {
        int t0 = 2 * kt, t1 = 2 * kt + 1;
        pa[kt][0] = pk2(S[t0][0] * inv0, S[t0][1] * inv0);
        pa[kt][1] = pk2(S[t0][2] * inv1, S[t0][3] * inv1);
        if (t1 < 9) {
            pa[kt][2] = pk2(S[t1][0] * inv0, S[t1][1] * inv0);
            pa[kt][3] = pk2(S[t1][2] * inv1, S[t1][3] * inv1);
        } else {
            pa[kt][2] = 0u; pa[kt][3] = 0u;
        }
    }

    float dO[4][4];
#pragma unroll
    for (int i = 0; i < 4; i++)
        dO[i][0] = dO[i][1] = dO[i][2] = dO[i][3] = 0.f;
    const __half* Bv = Vb + (lane & 15) * 88 + ((lane >> 4) * 8);
#pragma unroll
    for (int kt = 0; kt < 5; kt++) {
        uint32_t b0, b1, b2, b3;
        LDSM4(b0, b1, b2, b3, Bv + kt * 16);
        MMA16816(dO[0], pa[kt][0], pa[kt][1], pa[kt][2], pa[kt][3], b0, b2);
        MMA16816(dO[1], pa[kt][0], pa[kt][1], pa[kt][2], pa[kt][3], b1, b3);
        LDSM4(b0, b1, b2, b3, Bv + 16 * 88 + kt * 16);
        MMA16816(dO[2], pa[kt][0], pa[kt][1], pa[kt][2], pa[kt][3], b0, b2);
        MMA16816(dO[3], pa[kt][0], pa[kt][1], pa[kt][2], pa[kt][3], b1, b3);
    }
#pragma unroll
    for (int nt8 = 0; nt8 < 4; nt8++) {
        int c = h * 32 + nt8 * 8 + cbase;
        *(__half2*)(Os + r0 * 264 + c) = __floats2half2_rn(dO[nt8][0], dO[nt8][1]);
        *(__half2*)(Os + r1 * 264 + c) = __floats2half2_rn(dO[nt8][2], dO[nt8][3]);
    }
}

__global__ void __launch_bounds__(NTHREADS, 1)
win_attn_mma(const float* __restrict__ x,
             const float* __restrict__ qkv_b,
             const float* __restrict__ tab,
             const float* __restrict__ proj_b,
             float* __restrict__ out)
{
    extern __shared__ char smraw[];
    __half* Xs = (__half*)(smraw + XS_B);
    __half* Os = (__half*)(smraw + OS_B);
    __half* Wh = (__half*)(smraw + WH_B);
    __half* Tb = (__half*)(smraw + TB_B);
    unsigned char* IdxT = (unsigned char*)(smraw + IX_B);
    __half* Bq = (__half*)(smraw + BQ_B);
    float*  Bp = (float*)(smraw + BP_B);
    __half* PB = Xs;   // proj chunk2 B reuses dead Xs region in epilogue

    const int tid  = threadIdx.x;
    const int warp = tid >> 5;
    const int lane = tid & 31;
    const int win  = blockIdx.x;

    // ---------------- prologue: stage inputs + head-0 weights ----------------
    const float2* xg = (const float2*)(x + (size_t)win * NTOK * CDIM);
    for (int i = tid; i < NTOK * 128; i += NTHREADS) {
        int r = i >> 7, c2 = i & 127;
        float2 v = xg[i];
        *(__half2*)(Xs + r * 264 + 2 * c2) = __floats2half2_rn(v.x, v.y);
    }
    for (int i = tid; i < 14 * 132; i += NTHREADS) {   // zero pad rows 66..79
        int r = 66 + i / 132, c2 = i % 132;
        *((uint32_t*)(Xs + r * 264) + c2) = 0u;
    }
    for (int i = tid; i < 1800; i += NTHREADS) Tb[i] = __float2half_rn(tab[i]);
    for (int i = tid; i < 4096; i += NTHREADS) {
        int p = i >> 6, q = i & 63;
        int dy = (p >> 3) - (q >> 3) + 7;
        int dx = (p & 7) - (q & 7) + 7;
        IdxT[i] = (unsigned char)(dy * 15 + dx);
    }
    for (int i = tid; i < 768; i += NTHREADS) Bq[i] = __float2half_rn(qkv_b[i]);
    if (tid < 256) Bp[tid] = proj_b[tid];
    stage_head(0, Wh, tid, NTHREADS);
    __syncthreads();

    // ======== pipelined head loop: GEMM1(h) || attention(h-1) || stage(h+1) ========
    for (int h = 0; h < NHEAD; h++) {
        int bufW = h & 1;
        char* qkvW = smraw + QKV_B + bufW * QKV_STR_B;
        if (warp < 6) {
            gemm1_col(h, warp, lane, Xs, Wh + bufW * WH_STRIDE, Bq,
                      (__half*)qkvW, (__half*)(qkvW + 6400), (__half*)(qkvW + 12160));
        } else if (warp < 11) {
            if (h > 0) {
                char* qkvR = smraw + QKV_B + ((h - 1) & 1) * QKV_STR_B;
                attn_tile(h - 1, warp - 6, lane,
                          (const __half*)qkvR, (const __half*)(qkvR + 6400),
                          (const __half*)(qkvR + 12160), Os, Tb, IdxT);
            }
        } else {
            if (h < 7) stage_head(h + 1, Wh + ((h + 1) & 1) * WH_STRIDE, tid - 352, 160);
            else       stage_wp(0, 96, Wh, tid - 352, 160);   // proj rows 0..95 -> Wh[0]
        }
        __syncthreads();
    }

    // ======== epilogue: attention(7) || stage proj rows 96..255 ========
    {
        char* qkvR = smraw + QKV_B + 1 * QKV_STR_B;   // head 7 buffer
        if (warp < 5) {
            attn_tile(7, warp, lane,
                      (const __half*)qkvR, (const __half*)(qkvR + 6400),
                      (const __half*)(qkvR + 12160), Os, Tb, IdxT);
        } else {
            // 352 threads: rows 96..191 -> Wh[1], rows 192..255 -> PB (Xs region)
            for (int i = tid - 160; i < 5120; i += 352) {
                int o = i >> 5, kk = (i & 31) * 8;
                uint4 v = *(const uint4*)(g_Wp + (96 + o) * 256 + kk);
                if (o < 96) *(uint4*)(Wh + WH_STRIDE + o * 264 + kk) = v;
                else        *(uint4*)(PB + (o - 96) * 264 + kk) = v;
            }
        }
    }
    __syncthreads();

    // ======== projection: single phase, 16 n16-column jobs ========
    {
        int job = warp;
        const __half* Brow;
        if (job < 6)
            Brow = Wh + (job * 16 + (lane & 15)) * 264 + ((lane >> 4) * 8);
        else if (job < 12)
            Brow = Wh + WH_STRIDE + ((job - 6) * 16 + (lane & 15)) * 264 + ((lane >> 4) * 8);
        else
            Brow = PB + ((job - 12) * 16 + (lane & 15)) * 264 + ((lane >> 4) * 8);

        float acc[5][2][4];
#pragma unroll
        for (int i = 0; i < 5; i++)
#pragma unroll
            for (int j = 0; j < 2; j++)
                acc[i][j][0] = acc[i][j][1] = acc[i][j][2] = acc[i][j][3] = 0.f;
        const __half* Arow = Os + (lane & 15) * 264 + ((lane >> 4) * 8);
#pragma unroll
        for (int ks = 0; ks < 16; ks++) {
            uint32_t b0, b1, b2, b3;
            LDSM4(b0, b1, b2, b3, Brow + ks * 16);
#pragma unroll
            for (int mt = 0; mt < 5; mt++) {
                uint32_t a0, a1, a2, a3;
                LDSM4(a0, a1, a2, a3, Arow + mt * 16 * 264 + ks * 16);
                MMA16816(acc[mt][0], a0, a1, a2, a3, b0, b2);
                MMA16816(acc[mt][1], a0, a1, a2, a3, b1, b3);
            }
        }
#pragma unroll
        for (int st = 0; st < 2; st++) {
            int cc = job * 16 + st * 8 + (lane & 3) * 2;
            float b0v = Bp[cc], b1v = Bp[cc + 1];
#pragma unroll
            for (int mt = 0; mt < 5; mt++) {
                int r0 = mt * 16 + (lane >> 2);
#pragma unroll
                for (int part = 0; part < 2; part++) {
                    int r = r0 + part * 8;
                    if (r < NTOK) {
                        float2 v;
                        v.x = acc[mt][st][part * 2 + 0] + b0v;
                        v.y = acc[mt][st][part * 2 + 1] + b1v;
                        *(float2*)(out + ((size_t)win * NTOK + r) * CDIM + cc) = v;
                    }
                }
            }
        }
    }
}

extern "C" void kernel_launch(void* const* d_in, const int* in_sizes, int n_in,
                              void* d_out, int out_size) {
    (void)in_sizes; (void)n_in; (void)out_size;
    const float* x      = (const float*)d_in[0];
    const float* qkv_w  = (const float*)d_in[1];
    const float* qkv_b  = (const float*)d_in[2];
    const float* tab    = (const float*)d_in[3];
    const float* proj_w = (const float*)d_in[4];
    const float* proj_b = (const float*)d_in[5];
    float* out = (float*)d_out;

    prep_kernel<<<768, 256>>>(qkv_w, proj_w);

    cudaFuncSetAttribute(win_attn_mma,
                         cudaFuncAttributeMaxDynamicSharedMemorySize, SMEM_BYTES);
    win_attn_mma<<<NWIN, NTHREADS, SMEM_BYTES>>>(
        x, qkv_b, tab, proj_b, out);
}

// round 17
// speedup vs baseline: 1.0349x; 1.0349x over previous
#include <cuda_runtime.h>
#include <cuda_fp16.h>
#include <stdint.h>
#include <math.h>

#define NWIN     2048
#define NTOK     66
#define CDIM     256
#define NHEAD    8
#define NTHREADS 512

// fp16 weight copies, prepared at the start of every launch (graph-safe, deterministic)
__device__ __align__(16) __half g_Wq[768 * 256];
__device__ __align__(16) __half g_Wp[256 * 256];

__global__ void prep_kernel(const float* __restrict__ qkv_w,
                            const float* __restrict__ proj_w) {
    int i = blockIdx.x * blockDim.x + threadIdx.x;
    if (i < 768 * 256) g_Wq[i] = __float2half_rn(qkv_w[i]);
    if (i < 256 * 256) g_Wp[i] = __float2half_rn(proj_w[i]);
}

// ---- shared memory layout (byte offsets) ----
// Xs [80][264] h (dead after last GEMM1; reused as proj rows 192..255)
// Os [80][264] h ; Wh [192][264] h (2-head pair / proj rows 0..191)
// QKV 2 x {Qs[80][40], Ks[72][40], Vt[32][88]}
// Tb fp16[1800] ; IdxT u8[4096] ; Bq fp16[768] ; Bp f32[256]
#define XS_B   0
#define OS_B   42240
#define WH_B   84480
#define QS_B   185856
#define KS_B   198656
#define VT_B   210176
#define TB_B   221440
#define IX_B   225040
#define BQ_B   229136
#define BP_B   230672
#define SMEM_BYTES 231696

__device__ __forceinline__ uint32_t sptr(const void* p) {
    return (uint32_t)__cvta_generic_to_shared(p);
}

#define LDSM4(r0, r1, r2, r3, p)                                              \
    asm volatile("ldmatrix.sync.aligned.m8n8.x4.shared.b16 {%0,%1,%2,%3}, [%4];" \
                 : "=r"(r0), "=r"(r1), "=r"(r2), "=r"(r3) : "r"(sptr(p)))

#define LDSM2(r0, r1, p)                                                      \
    asm volatile("ldmatrix.sync.aligned.m8n8.x2.shared.b16 {%0,%1}, [%2];"    \
                 : "=r"(r0), "=r"(r1) : "r"(sptr(p)))

#define MMA16816(d, a0, a1, a2, a3, b0, b1)                                   \
    asm volatile("mma.sync.aligned.m16n8k16.row.col.f32.f16.f16.f32 "         \
                 "{%0,%1,%2,%3}, {%4,%5,%6,%7}, {%8,%9}, {%0,%1,%2,%3};"      \
                 : "+f"((d)[0]), "+f"((d)[1]), "+f"((d)[2]), "+f"((d)[3])     \
                 : "r"(a0), "r"(a1), "r"(a2), "r"(a3), "r"(b0), "r"(b1))

__device__ __forceinline__ uint32_t pk2(float x, float y) {
    __half2 h = __floats2half2_rn(x, y);
    return *(uint32_t*)&h;
}

// stage 2 heads' qkv weights (pair p -> heads 2p, 2p+1) into Wh[192][264]
__device__ __forceinline__ void stage_qkv_pair(int pair, __half* Wh,
                                               int t0, int nthr) {
    for (int i = t0; i < 6144; i += nthr) {
        int o = i >> 5, kk = (i & 31) * 8;
        int hh = o / 96, ol = o % 96;
        int s = ol >> 5, jj = ol & 31;
        int head = pair * 2 + hh;
        *(uint4*)(Wh + o * 264 + kk) =
            *(const uint4*)(g_Wq + ((s * 256 + head * 32 + jj) * 256 + kk));
    }
}

__global__ void __launch_bounds__(NTHREADS, 1)
win_attn_mma(const float* __restrict__ x,
             const float* __restrict__ qkv_b,
             const float* __restrict__ tab,
             const float* __restrict__ proj_b,
             float* __restrict__ out)
{
    extern __shared__ char smraw[];
    __half* Xs = (__half*)(smraw + XS_B);
    __half* Os = (__half*)(smraw + OS_B);
    __half* Wh = (__half*)(smraw + WH_B);
    __half* Qs = (__half*)(smraw + QS_B);
    __half* Ks = (__half*)(smraw + KS_B);
    __half* Vt = (__half*)(smraw + VT_B);
    __half* Tb = (__half*)(smraw + TB_B);
    unsigned char* IdxT = (unsigned char*)(smraw + IX_B);
    __half* Bq = (__half*)(smraw + BQ_B);
    float*  Bp = (float*)(smraw + BP_B);
    __half* PB = Xs;   // proj rows 192..255 reuse dead Xs region

    const int tid  = threadIdx.x;
    const int warp = tid >> 5;
    const int lane = tid & 31;
    const int win  = blockIdx.x;
    const float scale = 0.17677669529663687f;  // 1/sqrt(32)

    // ---------------- prologue: stage inputs + pair-0 weights ----------------
    const float2* xg = (const float2*)(x + (size_t)win * NTOK * CDIM);
    for (int i = tid; i < NTOK * 128; i += NTHREADS) {
        int r = i >> 7, c2 = i & 127;
        float2 v = xg[i];
        *(__half2*)(Xs + r * 264 + 2 * c2) = __floats2half2_rn(v.x, v.y);
    }
    for (int i = tid; i < 14 * 132; i += NTHREADS) {   // zero pad rows 66..79
        int r = 66 + i / 132, c2 = i % 132;
        *((uint32_t*)(Xs + r * 264) + c2) = 0u;
    }
    for (int i = tid; i < 1800; i += NTHREADS) Tb[i] = __float2half_rn(tab[i]);
    for (int i = tid; i < 4096; i += NTHREADS) {
        int p = i >> 6, q = i & 63;
        int dy = (p >> 3) - (q >> 3) + 7;
        int dx = (p & 7) - (q & 7) + 7;
        IdxT[i] = (unsigned char)(dy * 15 + dx);
    }
    for (int i = tid; i < 768; i += NTHREADS) Bq[i] = __float2half_rn(qkv_b[i]);
    if (tid < 256) Bp[tid] = proj_b[tid];
    stage_qkv_pair(0, Wh, tid, NTHREADS);
    __syncthreads();

    // ================= 4 iterations of 2 heads each =================
    for (int it = 0; it < 4; it++) {
        // ---- GEMM1: 10 (head, m-tile) jobs, full 6-col slice per job ----
        if (warp < 10) {
            int hh = warp >= 5, mt = warp - hh * 5;
            int h = it * 2 + hh;
            float acc[6][2][4];
#pragma unroll
            for (int c = 0; c < 6; c++)
#pragma unroll
                for (int j = 0; j < 2; j++)
                    acc[c][j][0] = acc[c][j][1] = acc[c][j][2] = acc[c][j][3] = 0.f;

            const __half* Arow = Xs + (mt * 16 + (lane & 15)) * 264 + ((lane >> 4) * 8);
            const __half* Brow = Wh + (hh * 96 + (lane & 15)) * 264 + ((lane >> 4) * 8);
#pragma unroll
            for (int ks = 0; ks < 16; ks++) {
                uint32_t a0, a1, a2, a3;
                LDSM4(a0, a1, a2, a3, Arow + ks * 16);
#pragma unroll
                for (int c = 0; c < 6; c++) {
                    uint32_t b0, b1, b2, b3;
                    LDSM4(b0, b1, b2, b3, Brow + c * 16 * 264 + ks * 16);
                    MMA16816(acc[c][0], a0, a1, a2, a3, b0, b2);
                    MMA16816(acc[c][1], a0, a1, a2, a3, b1, b3);
                }
            }
            __half* Qsh = Qs + hh * 3200;
            __half* Ksh = Ks + hh * 2880;
            __half* Vth = Vt + hh * 2816;
#pragma unroll
            for (int c = 0; c < 6; c++) {
#pragma unroll
                for (int st = 0; st < 2; st++) {
                    int cb = c * 16 + st * 8 + (lane & 3) * 2;
                    int s = cb >> 5, dd = cb & 31;
                    float b0v = __half2float(Bq[s * 256 + h * 32 + dd]);
                    float b1v = __half2float(Bq[s * 256 + h * 32 + dd + 1]);
                    int r0 = mt * 16 + (lane >> 2);
#pragma unroll
                    for (int part = 0; part < 2; part++) {
                        int r = r0 + part * 8;
                        float v0 = acc[c][st][part * 2 + 0] + b0v;
                        float v1 = acc[c][st][part * 2 + 1] + b1v;
                        if (s == 0) {
                            *(__half2*)(Qsh + r * 40 + dd) =
                                __floats2half2_rn(v0 * scale, v1 * scale);
                        } else if (s == 1) {
                            if (r < 72)
                                *(__half2*)(Ksh + r * 40 + dd) = __floats2half2_rn(v0, v1);
                        } else {
                            Vth[dd * 88 + r]       = __float2half_rn(v0);
                            Vth[(dd + 1) * 88 + r] = __float2half_rn(v1);
                        }
                    }
                }
            }
        }
        __syncthreads();

        if (warp < 10) {
            // ---- attention for (m-tile, head): all in registers ----
            const int mt = warp >> 1, hh = warp & 1;
            const int h = it * 2 + hh;
            const __half* Qsh = Qs + hh * 3200;
            const __half* Ksh = Ks + hh * 2880;
            const __half* Vth = Vt + hh * 2816;
            const int r0 = mt * 16 + (lane >> 2);
            const int r1 = r0 + 8;
            const int cbase = (lane & 3) * 2;

            const __half* Aq = Qsh + (mt * 16 + (lane & 15)) * 40 + ((lane >> 4) * 8);
            uint32_t qa[2][4];
            LDSM4(qa[0][0], qa[0][1], qa[0][2], qa[0][3], Aq);
            LDSM4(qa[1][0], qa[1][1], qa[1][2], qa[1][3], Aq + 16);

            float S[9][4];
#pragma unroll
            for (int nt = 0; nt < 9; nt++) {
                S[nt][0] = S[nt][1] = S[nt][2] = S[nt][3] = 0.f;
                const __half* Bk = Ksh + (nt * 8 + (lane & 7)) * 40 + (((lane >> 3) & 1) * 8);
                uint32_t b0, b1;
                LDSM2(b0, b1, Bk);
                MMA16816(S[nt], qa[0][0], qa[0][1], qa[0][2], qa[0][3], b0, b1);
                LDSM2(b0, b1, Bk + 16);
                MMA16816(S[nt], qa[1][0], qa[1][1], qa[1][2], qa[1][3], b0, b1);
            }

#pragma unroll
            for (int nt = 0; nt < 9; nt++) {
#pragma unroll
                for (int e = 0; e < 2; e++) {
                    int c = nt * 8 + cbase + e;
                    if (c >= 66) {
                        S[nt][e] = -1e30f; S[nt][2 + e] = -1e30f;
                    } else if (c >= 2) {
                        int q = c - 2;
                        if (r0 >= 2 && r0 < 66)
                            S[nt][e]     += __half2float(Tb[(int)IdxT[(r0 - 2) * 64 + q] * 8 + h]);
                        if (r1 < 66)
                            S[nt][2 + e] += __half2float(Tb[(int)IdxT[(r1 - 2) * 64 + q] * 8 + h]);
                    }
                }
            }

            float m0 = -1e30f, m1 = -1e30f;
#pragma unroll
            for (int nt = 0; nt < 9; nt++) {
                m0 = fmaxf(m0, fmaxf(S[nt][0], S[nt][1]));
                m1 = fmaxf(m1, fmaxf(S[nt][2], S[nt][3]));
            }
            m0 = fmaxf(m0, __shfl_xor_sync(0xffffffffu, m0, 1));
            m0 = fmaxf(m0, __shfl_xor_sync(0xffffffffu, m0, 2));
            m1 = fmaxf(m1, __shfl_xor_sync(0xffffffffu, m1, 1));
            m1 = fmaxf(m1, __shfl_xor_sync(0xffffffffu, m1, 2));
            float s0 = 0.f, s1 = 0.f;
#pragma unroll
            for (int nt = 0; nt < 9; nt++) {
                S[nt][0] = __expf(S[nt][0] - m0); s0 += S[nt][0];
                S[nt][1] = __expf(S[nt][1] - m0); s0 += S[nt][1];
                S[nt][2] = __expf(S[nt][2] - m1); s1 += S[nt][2];
                S[nt][3] = __expf(S[nt][3] - m1); s1 += S[nt][3];
            }
            s0 += __shfl_xor_sync(0xffffffffu, s0, 1);
            s0 += __shfl_xor_sync(0xffffffffu, s0, 2);
            s1 += __shfl_xor_sync(0xffffffffu, s1, 1);
            s1 += __shfl_xor_sync(0xffffffffu, s1, 2);
            float inv0 = __frcp_rn(s0), inv1 = __frcp_rn(s1);

            uint32_t pa[5][4];
#pragma unroll
            for (int kt = 0; kt < 5; kt++) {
                int t0 = 2 * kt, t1 = 2 * kt + 1;
                pa[kt][0] = pk2(S[t0][0] * inv0, S[t0][1] * inv0);
                pa[kt][1] = pk2(S[t0][2] * inv1, S[t0][3] * inv1);
                if (t1 < 9) {
                    pa[kt][2] = pk2(S[t1][0] * inv0, S[t1][1] * inv0);
                    pa[kt][3] = pk2(S[t1][2] * inv1, S[t1][3] * inv1);
                } else {
                    pa[kt][2] = 0u; pa[kt][3] = 0u;
                }
            }

            float dO[4][4];
#pragma unroll
            for (int i = 0; i < 4; i++)
                dO[i][0] = dO[i][1] = dO[i][2] = dO[i][3] = 0.f;
            const __half* Bv = Vth + (lane & 15) * 88 + ((lane >> 4) * 8);
#pragma unroll
            for (int kt = 0; kt < 5; kt++) {
                uint32_t b0, b1, b2, b3;
                LDSM4(b0, b1, b2, b3, Bv + kt * 16);
                MMA16816(dO[0], pa[kt][0], pa[kt][1], pa[kt][2], pa[kt][3], b0, b2);
                MMA16816(dO[1], pa[kt][0], pa[kt][1], pa[kt][2], pa[kt][3], b1, b3);
                LDSM4(b0, b1, b2, b3, Bv + 16 * 88 + kt * 16);
                MMA16816(dO[2], pa[kt][0], pa[kt][1], pa[kt][2], pa[kt][3], b0, b2);
                MMA16816(dO[3], pa[kt][0], pa[kt][1], pa[kt][2], pa[kt][3], b1, b3);
            }
#pragma unroll
            for (int nt8 = 0; nt8 < 4; nt8++) {
                int c = h * 32 + nt8 * 8 + cbase;
                *(__half2*)(Os + r0 * 264 + c) = __floats2half2_rn(dO[nt8][0], dO[nt8][1]);
                *(__half2*)(Os + r1 * 264 + c) = __floats2half2_rn(dO[nt8][2], dO[nt8][3]);
            }
        } else {
            // warps 10-15: stage next pair, or ALL proj weights on last iter
            int t0 = tid - 320;
            if (it < 3) {
                stage_qkv_pair(it + 1, Wh, t0, 192);
            } else {
                // proj rows 0..191 -> Wh, rows 192..255 -> PB (dead Xs region)
                for (int i = t0; i < 8192; i += 192) {
                    int o = i >> 5, kk = (i & 31) * 8;
                    uint4 v = *(const uint4*)(g_Wp + o * 256 + kk);
                    if (o < 192) *(uint4*)(Wh + o * 264 + kk) = v;
                    else         *(uint4*)(PB + (o - 192) * 264 + kk) = v;
                }
            }
        }
        __syncthreads();
    }

    // ======== projection: single phase, 16 n16-column jobs ========
    {
        int job = warp;
        const __half* Brow = (job < 12)
            ? Wh + (job * 16 + (lane & 15)) * 264 + ((lane >> 4) * 8)
            : PB + ((job - 12) * 16 + (lane & 15)) * 264 + ((lane >> 4) * 8);

        float acc[5][2][4];
#pragma unroll
        for (int i = 0; i < 5; i++)
#pragma unroll
            for (int j = 0; j < 2; j++)
                acc[i][j][0] = acc[i][j][1] = acc[i][j][2] = acc[i][j][3] = 0.f;
        const __half* Arow = Os + (lane & 15) * 264 + ((lane >> 4) * 8);
#pragma unroll
        for (int ks = 0; ks < 16; ks++) {
            uint32_t b0, b1, b2, b3;
            LDSM4(b0, b1, b2, b3, Brow + ks * 16);
#pragma unroll
            for (int mt = 0; mt < 5; mt++) {
                uint32_t a0, a1, a2, a3;
                LDSM4(a0, a1, a2, a3, Arow + mt * 16 * 264 + ks * 16);
                MMA16816(acc[mt][0], a0, a1, a2, a3, b0, b2);
                MMA16816(acc[mt][1], a0, a1, a2, a3, b1, b3);
            }
        }
#pragma unroll
        for (int st = 0; st < 2; st++) {
            int cc = job * 16 + st * 8 + (lane & 3) * 2;
            float b0v = Bp[cc], b1v = Bp[cc + 1];
#pragma unroll
            for (int mt = 0; mt < 5; mt++) {
                int r0 = mt * 16 + (lane >> 2);
#pragma unroll
                for (int part = 0; part < 2; part++) {
                    int r = r0 + part * 8;
                    if (r < NTOK) {
                        float2 v;
                        v.x = acc[mt][st][part * 2 + 0] + b0v;
                        v.y = acc[mt][st][part * 2 + 1] + b1v;
                        *(float2*)(out + ((size_t)win * NTOK + r) * CDIM + cc) = v;
                    }
                }
            }
        }
    }
}

extern "C" void kernel_launch(void* const* d_in, const int* in_sizes, int n_in,
                              void* d_out, int out_size) {
    (void)in_sizes; (void)n_in; (void)out_size;
    const float* x      = (const float*)d_in[0];
    const float* qkv_w  = (const float*)d_in[1];
    const float* qkv_b  = (const float*)d_in[2];
    const float* tab    = (const float*)d_in[3];
    const float* proj_w = (const float*)d_in[4];
    const float* proj_b = (const float*)d_in[5];
    float* out = (float*)d_out;

    prep_kernel<<<768, 256>>>(qkv_w, proj_w);

    cudaFuncSetAttribute(win_attn_mma,
                         cudaFuncAttributeMaxDynamicSharedMemorySize, SMEM_BYTES);
    win_attn_mma<<<NWIN, NTHREADS, SMEM_BYTES>>>(
        x, qkv_b, tab, proj_b, out);
}